// round 1
// baseline (speedup 1.0000x reference)
#include <cuda_runtime.h>

#define N_ROWS 8192
#define M_COLS 8192
#define D_DIM  64

#define BM 128
#define BN 128
#define BK 32
#define PITCH (BM + 4)   // 132 floats: keeps 16B row alignment, breaks worst STS conflicts

// Precomputed per-row / per-col stats (device globals: no allocation allowed)
__device__ float g_a2[N_ROWS];
__device__ float g_pa[N_ROWS];   // 2 / (1 - a2)
__device__ float g_b2[M_COLS];
__device__ float g_qb[M_COLS];   // 1 / (1 - b2)

// One warp per row: squared norm + reciprocal terms. 16384 rows total.
__global__ void poincare_stats_kernel(const float* __restrict__ a,
                                      const float* __restrict__ b) {
    int warp = (blockIdx.x * blockDim.x + threadIdx.x) >> 5;
    int lane = threadIdx.x & 31;
    if (warp < N_ROWS) {
        const float* row = a + (size_t)warp * D_DIM;
        float v0 = row[lane];
        float v1 = row[lane + 32];
        float s = fmaf(v0, v0, v1 * v1);
        #pragma unroll
        for (int o = 16; o > 0; o >>= 1) s += __shfl_xor_sync(0xffffffffu, s, o);
        if (lane == 0) {
            g_a2[warp] = s;
            g_pa[warp] = 2.0f / (1.0f - s);
        }
    } else if (warp < N_ROWS + M_COLS) {
        int r = warp - N_ROWS;
        const float* row = b + (size_t)r * D_DIM;
        float v0 = row[lane];
        float v1 = row[lane + 32];
        float s = fmaf(v0, v0, v1 * v1);
        #pragma unroll
        for (int o = 16; o > 0; o >>= 1) s += __shfl_xor_sync(0xffffffffu, s, o);
        if (lane == 0) {
            g_b2[r] = s;
            g_qb[r] = 1.0f / (1.0f - s);
        }
    }
}

__device__ __forceinline__ float fast_sqrt(float x) {
    float r;
    asm("sqrt.approx.f32 %0, %1;" : "=f"(r) : "f"(x));
    return r;
}

// Fused: fp32 GEMM (dot products) + Poincare epilogue.
// Grid: (M/BN, N/BM), block: 256 threads (16x16), each thread owns 8x8 outputs.
__global__ void __launch_bounds__(256, 2)
poincare_main_kernel(const float* __restrict__ A,
                     const float* __restrict__ B,
                     float* __restrict__ out) {
    __shared__ float As[BK][PITCH];
    __shared__ float Bs[BK][PITCH];

    const int bm = blockIdx.y * BM;
    const int bn = blockIdx.x * BN;
    const int tid = threadIdx.x;
    const int tx = tid & 15;
    const int ty = tid >> 4;
    const int om = ty * 8;   // local row of 8x8 tile
    const int on = tx * 8;   // local col of 8x8 tile

    // loader mapping: 256 threads cover 32 rows x 8 float4 per pass
    const int lrow = tid >> 3;          // 0..31
    const int lk   = (tid & 7) << 2;    // 0,4,...,28

    float acc[8][8];
    #pragma unroll
    for (int i = 0; i < 8; i++)
        #pragma unroll
        for (int j = 0; j < 8; j++) acc[i][j] = 0.0f;

    #pragma unroll
    for (int kk = 0; kk < D_DIM; kk += BK) {
        // ---- stage BKxBM tiles (transposed) into smem ----
        #pragma unroll
        for (int r = 0; r < BM; r += 32) {
            const float4 va = *reinterpret_cast<const float4*>(
                A + (size_t)(bm + r + lrow) * D_DIM + kk + lk);
            As[lk + 0][r + lrow] = va.x;
            As[lk + 1][r + lrow] = va.y;
            As[lk + 2][r + lrow] = va.z;
            As[lk + 3][r + lrow] = va.w;
            const float4 vb = *reinterpret_cast<const float4*>(
                B + (size_t)(bn + r + lrow) * D_DIM + kk + lk);
            Bs[lk + 0][r + lrow] = vb.x;
            Bs[lk + 1][r + lrow] = vb.y;
            Bs[lk + 2][r + lrow] = vb.z;
            Bs[lk + 3][r + lrow] = vb.w;
        }
        __syncthreads();

        // ---- outer-product accumulation ----
        #pragma unroll 4
        for (int k = 0; k < BK; k++) {
            float ra[8], rb[8];
            *reinterpret_cast<float4*>(&ra[0]) =
                *reinterpret_cast<const float4*>(&As[k][om]);
            *reinterpret_cast<float4*>(&ra[4]) =
                *reinterpret_cast<const float4*>(&As[k][om + 4]);
            *reinterpret_cast<float4*>(&rb[0]) =
                *reinterpret_cast<const float4*>(&Bs[k][on]);
            *reinterpret_cast<float4*>(&rb[4]) =
                *reinterpret_cast<const float4*>(&Bs[k][on + 4]);
            #pragma unroll
            for (int i = 0; i < 8; i++)
                #pragma unroll
                for (int j = 0; j < 8; j++)
                    acc[i][j] = fmaf(ra[i], rb[j], acc[i][j]);
        }
        __syncthreads();
    }

    // ---- fused Poincare epilogue ----
    const int gi = bm + om;
    const int gj = bn + on;

    float b2r[8], qbr[8];
    #pragma unroll
    for (int j = 0; j < 8; j++) {
        b2r[j] = g_b2[gj + j];
        qbr[j] = g_qb[gj + j];
    }

    #pragma unroll
    for (int i = 0; i < 8; i++) {
        const float a2i = g_a2[gi + i];
        const float pai = g_pa[gi + i];
        float res[8];
        #pragma unroll
        for (int j = 0; j < 8; j++) {
            // squared distance via GEMM trick, clamped at 0 (matches reference)
            float sq = fmaf(-2.0f, acc[i][j], a2i + b2r[j]);
            sq = fmaxf(sq, 0.0f);
            const float d = fast_sqrt(sq);
            // y = 2*d / ((1-a2)(1-b2)) with precomputed reciprocals
            const float y = d * (pai * qbr[j]);
            // inner^2 - 1 = y*(y+2), cancellation-free
            const float t  = fmaf(y, y, y + y);
            const float st = fast_sqrt(t);
            // arcosh(1+y) = log(1 + y + sqrt(y(y+2)))
            res[j] = __logf(1.0f + y + st);
        }
        float4* o = reinterpret_cast<float4*>(out + (size_t)(gi + i) * M_COLS + gj);
        o[0] = *reinterpret_cast<float4*>(&res[0]);
        o[1] = *reinterpret_cast<float4*>(&res[4]);
    }
}

extern "C" void kernel_launch(void* const* d_in, const int* in_sizes, int n_in,
                              void* d_out, int out_size) {
    const float* a = (const float*)d_in[0];
    const float* b = (const float*)d_in[1];
    float* out = (float*)d_out;

    // stats: one warp per row, (N+M) warps = 16384 -> 2048 blocks x 256 threads
    poincare_stats_kernel<<<(N_ROWS + M_COLS) / 8, 256>>>(a, b);

    dim3 grid(M_COLS / BN, N_ROWS / BM);
    poincare_main_kernel<<<grid, 256>>>(a, b, out);
}

// round 3
// speedup vs baseline: 1.9464x; 1.9464x over previous
#include <cuda_runtime.h>
#include <cuda_fp16.h>
#include <cstdint>

#define NR 8192
#define MC 8192
#define DD 64

// ---------------- device-global staging (no allocation allowed) ----------------
__device__ __align__(16) __half g_ah[NR * DD];
__device__ __align__(16) __half g_al[NR * DD];
__device__ __align__(16) __half g_bh[MC * DD];
__device__ __align__(16) __half g_bl[MC * DD];
// per-row stats: x = |p|^2, y = 2/(1-|a|^2) for a-rows, 1/(1-|b|^2) for b-rows
__device__ float2 g_apa[NR];
__device__ float2 g_bq[MC];

// ---------------- helpers ----------------
__device__ __forceinline__ float fast_sqrt(float x) {
    float r; asm("sqrt.approx.f32 %0, %1;" : "=f"(r) : "f"(x)); return r;
}
__device__ __forceinline__ uint32_t smem_u32(const void* p) {
    uint32_t a;
    asm("{ .reg .u64 t; cvta.to.shared.u64 t, %1; cvt.u32.u64 %0, t; }" : "=r"(a) : "l"(p));
    return a;
}
#define CP_ASYNC16(dst, src) \
    asm volatile("cp.async.cg.shared.global [%0], [%1], 16;" :: "r"(dst), "l"(src) : "memory")
#define CP_COMMIT() asm volatile("cp.async.commit_group;" ::: "memory")
#define CP_WAIT0()  asm volatile("cp.async.wait_group 0;" ::: "memory")

#define LDSM4(R, a) \
    asm volatile("ldmatrix.sync.aligned.m8n8.x4.shared.b16 {%0,%1,%2,%3}, [%4];" \
        : "=r"((R)[0]), "=r"((R)[1]), "=r"((R)[2]), "=r"((R)[3]) : "r"(a))

#define MMA16816(d, a, b0, b1) \
    asm volatile("mma.sync.aligned.m16n8k16.row.col.f32.f16.f16.f32 " \
        "{%0,%1,%2,%3}, {%4,%5,%6,%7}, {%8,%9}, {%0,%1,%2,%3};" \
        : "+f"((d)[0]), "+f"((d)[1]), "+f"((d)[2]), "+f"((d)[3]) \
        : "r"((a)[0]), "r"((a)[1]), "r"((a)[2]), "r"((a)[3]), "r"(b0), "r"(b1))

// ---------------- prep: norms + reciprocal terms + fp16 hi/lo split ----------------
__global__ void poincare_prep_kernel(const float* __restrict__ a,
                                     const float* __restrict__ b) {
    int warp = (blockIdx.x * blockDim.x + threadIdx.x) >> 5;
    int lane = threadIdx.x & 31;
    const float* row;
    __half *dh, *dl;
    bool isA = warp < NR;
    int r = isA ? warp : warp - NR;
    if (isA) { row = a + (size_t)r * DD; dh = g_ah + (size_t)r * DD; dl = g_al + (size_t)r * DD; }
    else     { row = b + (size_t)r * DD; dh = g_bh + (size_t)r * DD; dl = g_bl + (size_t)r * DD; }

    float v0 = row[lane], v1 = row[lane + 32];
    // hi/lo split
    __half h0 = __float2half_rn(v0);
    __half l0 = __float2half_rn(v0 - __half2float(h0));
    __half h1 = __float2half_rn(v1);
    __half l1 = __float2half_rn(v1 - __half2float(h1));
    dh[lane] = h0;  dh[lane + 32] = h1;
    dl[lane] = l0;  dl[lane + 32] = l1;

    float s = fmaf(v0, v0, v1 * v1);
    #pragma unroll
    for (int o = 16; o > 0; o >>= 1) s += __shfl_xor_sync(0xffffffffu, s, o);
    if (lane == 0) {
        if (isA) g_apa[r] = make_float2(s, 2.0f / (1.0f - s));
        else     g_bq[r]  = make_float2(s, 1.0f / (1.0f - s));
    }
}

// ---------------- main: fp16-split HMMA GEMM + fused Poincare epilogue ----------------
// CTA tile 128(M: a-rows) x 128(N: b-rows), K = 64 in one shot.
// 8 warps: warp grid 2(M) x 4(N); warp tile 64x32.
#define PITCH 144   // smem row pitch bytes (128 data + 16 pad) -> ldmatrix conflict-free
#define TILE_BYTES (128 * PITCH)

__global__ void __launch_bounds__(256)
poincare_hmma_kernel(float* __restrict__ out) {
    extern __shared__ char smem[];
    char* sAh = smem;
    char* sAl = smem + TILE_BYTES;
    char* sBh = smem + 2 * TILE_BYTES;
    char* sBl = smem + 3 * TILE_BYTES;

    const int tid = threadIdx.x;
    const int lane = tid & 31;
    const int wid = tid >> 5;
    const int wm = wid >> 2;       // 0..1
    const int wn = wid & 3;        // 0..3

    const int row0 = blockIdx.y * 128;   // a-rows
    const int col0 = blockIdx.x * 128;   // b-rows

    // ---- stage all 4 tiles via cp.async (each 128 rows x 128B) ----
    {
        const uint32_t sb = smem_u32(smem);
        #pragma unroll
        for (int t = 0; t < 4; t++) {
            int chunk = tid + 256 * t;      // 0..1023
            int r = chunk >> 3;
            int kc = chunk & 7;
            uint32_t doff = (uint32_t)(r * PITCH + kc * 16);
            CP_ASYNC16(sb + 0 * TILE_BYTES + doff, g_ah + (size_t)(row0 + r) * DD + kc * 8);
            CP_ASYNC16(sb + 1 * TILE_BYTES + doff, g_al + (size_t)(row0 + r) * DD + kc * 8);
            CP_ASYNC16(sb + 2 * TILE_BYTES + doff, g_bh + (size_t)(col0 + r) * DD + kc * 8);
            CP_ASYNC16(sb + 3 * TILE_BYTES + doff, g_bl + (size_t)(col0 + r) * DD + kc * 8);
        }
        CP_COMMIT();
        CP_WAIT0();
    }
    __syncthreads();

    // ---- accumulators: 4 M-frags x 4 N-frags x 4 floats ----
    float acc[4][4][4];
    #pragma unroll
    for (int i = 0; i < 4; i++)
        #pragma unroll
        for (int j = 0; j < 4; j++)
            #pragma unroll
            for (int q = 0; q < 4; q++) acc[i][j][q] = 0.0f;

    // ldmatrix lane addressing
    const uint32_t a_row  = (uint32_t)(wm * 64 + (lane & 15));
    const uint32_t a_koff = (uint32_t)((lane >> 4) * 16);
    const uint32_t b_row  = (uint32_t)(wn * 32 + ((lane & 16) >> 1) + (lane & 7));
    const uint32_t b_koff = (uint32_t)(((lane >> 3) & 1) * 16);

    const uint32_t uAh = smem_u32(sAh), uAl = smem_u32(sAl);
    const uint32_t uBh = smem_u32(sBh), uBl = smem_u32(sBl);

    #pragma unroll
    for (int ks = 0; ks < 4; ks++) {
        const uint32_t kb = (uint32_t)(ks * 32);
        uint32_t Ah[4][4], Al[4][4];
        #pragma unroll
        for (int mf = 0; mf < 4; mf++) {
            uint32_t off = (a_row + mf * 16) * PITCH + kb + a_koff;
            LDSM4(Ah[mf], uAh + off);
            LDSM4(Al[mf], uAl + off);
        }
        uint32_t Bh[2][4], Bl[2][4];
        #pragma unroll
        for (int nh = 0; nh < 2; nh++) {
            uint32_t off = (b_row + nh * 16) * PITCH + kb + b_koff;
            LDSM4(Bh[nh], uBh + off);
            LDSM4(Bl[nh], uBl + off);
        }
        #pragma unroll
        for (int mf = 0; mf < 4; mf++) {
            #pragma unroll
            for (int nf = 0; nf < 4; nf++) {
                uint32_t bh0 = Bh[nf >> 1][(nf & 1) * 2], bh1 = Bh[nf >> 1][(nf & 1) * 2 + 1];
                uint32_t bl0 = Bl[nf >> 1][(nf & 1) * 2], bl1 = Bl[nf >> 1][(nf & 1) * 2 + 1];
                MMA16816(acc[mf][nf], Ah[mf], bh0, bh1);   // hi*hi
                MMA16816(acc[mf][nf], Ah[mf], bl0, bl1);   // hi*lo
                MMA16816(acc[mf][nf], Al[mf], bh0, bh1);   // lo*hi
            }
        }
    }

    // ---- fused Poincare epilogue ----
    // c frag: c0,c1 = (row = lane/4, col = 2*(lane%4)+{0,1}); c2,c3 = row+8
    const int er = row0 + wm * 64 + (lane >> 2);
    const int ec = col0 + wn * 32 + 2 * (lane & 3);

    float2 rs[4][2];   // row stats per mf: {row, row+8}
    float2 cs[4][2];   // col stats per nf: {col, col+1}
    #pragma unroll
    for (int mf = 0; mf < 4; mf++) {
        rs[mf][0] = g_apa[er + mf * 16];
        rs[mf][1] = g_apa[er + mf * 16 + 8];
    }
    #pragma unroll
    for (int nf = 0; nf < 4; nf++) {
        cs[nf][0] = g_bq[ec + nf * 8];
        cs[nf][1] = g_bq[ec + nf * 8 + 1];
    }

    #pragma unroll
    for (int mf = 0; mf < 4; mf++) {
        #pragma unroll
        for (int nf = 0; nf < 4; nf++) {
            float res[4];
            #pragma unroll
            for (int q = 0; q < 4; q++) {
                float2 ra = rs[mf][q >> 1];
                float2 cb = cs[nf][q & 1];
                float sq = fmaf(-2.0f, acc[mf][nf][q], ra.x + cb.x);
                float d  = fast_sqrt(fmaxf(sq, 0.0f));
                float y  = d * (ra.y * cb.y);
                float tt = fmaf(y, y, y + y);
                res[q] = __logf(1.0f + y + fast_sqrt(tt));
            }
            size_t r0 = (size_t)(er + mf * 16) * MC + (ec + nf * 8);
            *reinterpret_cast<float2*>(out + r0)            = make_float2(res[0], res[1]);
            *reinterpret_cast<float2*>(out + r0 + 8 * MC)   = make_float2(res[2], res[3]);
        }
    }
}

extern "C" void kernel_launch(void* const* d_in, const int* in_sizes, int n_in,
                              void* d_out, int out_size) {
    const float* a = (const float*)d_in[0];
    const float* b = (const float*)d_in[1];
    float* out = (float*)d_out;

    cudaFuncSetAttribute(poincare_hmma_kernel,
                         cudaFuncAttributeMaxDynamicSharedMemorySize, 4 * TILE_BYTES);

    poincare_prep_kernel<<<(NR + MC) / 8, 256>>>(a, b);
    dim3 grid(MC / 128, NR / 128);
    poincare_hmma_kernel<<<grid, 256, 4 * TILE_BYTES>>>(out);
}